// round 1
// baseline (speedup 1.0000x reference)
#include <cuda_runtime.h>

// ConvSBS: fused 2-stage tensor-network contraction.
// channels: [2, 8, 128, 128, 4] f32   (ch0, ch1)
// cores:    [4, 2, 8, 8, 4, 4] f32    ([i, q, l, r, a, c])
// out:      [8, 127, 127, 16] f32
//
// out[b,y,x, p*8+q*4+r*2+s] = sum_{ijkl} M0^p[i,j] M1^q[j,k] M2^r[k,l] M3^s[l,i]
// where M_t^q[l,r] = sum_{a,c} core[t,q,l,r,a,c] * ch0[b,y+ht,x+wt,a] * ch1[b,y+ht,x+wt,c]
// with (ht,wt) = (t>>1, t&1).

#define BATCH 8
#define H 128
#define W 128
#define OH 127
#define OW 127
#define TOT_PIX (BATCH * OH * OW)

#define WARPS_PER_CTA 8
#define NCTAS 592

// smem (floats):
//   [0, 8192)                : cores relayout [iq][ac][lr]   (32 KB)
//   [8192 + w*576, ... )     : per-warp scratch (2304 B each)
//     stage1 M: [0,512)  (block (i*2+q)*64 + l*8 + r)
//     A blocks: [hi*68, +64)       hi = pq
//     Bt blocks:[288 + hi*68, +64) hi = rs   (Bt[rs][i][k] = B^{rs}[k][i])
#define CORES_F 8192
#define WARP_F  576
#define SMEM_F  (CORES_F + WARPS_PER_CTA * WARP_F)

__global__ void __launch_bounds__(256) convsbs_kernel(
    const float* __restrict__ channels,
    const float* __restrict__ cores,
    float* __restrict__ out)
{
    extern __shared__ float smem[];
    const int tid = threadIdx.x;

    // ---- relayout cores: [i][q][l][r][a][c] -> [i*2+q][a*4+c][l*8+r] ----
    for (int idx = tid; idx < 8192; idx += blockDim.x) {
        int c = idx & 3;
        int a = (idx >> 2) & 3;
        int r = (idx >> 4) & 7;
        int l = (idx >> 7) & 7;
        int q = (idx >> 10) & 1;
        int i = idx >> 11;
        smem[(((i * 2 + q) * 16 + (a * 4 + c)) << 6) + (l * 8 + r)] = cores[idx];
    }
    __syncthreads();

    const int warp = tid >> 5;
    const int lane = tid & 31;
    float* Ms = smem + CORES_F + warp * WARP_F;

    const float* __restrict__ ch0 = channels;
    const float* __restrict__ ch1 = channels + BATCH * H * W * 4;

    const int nwarps = gridDim.x * WARPS_PER_CTA;
    const int hi = lane >> 3;   // pq (A stage) / rs (B stage)
    const int lo = lane & 7;    // i index in both stages

    for (int pix = blockIdx.x * WARPS_PER_CTA + warp; pix < TOT_PIX; pix += nwarps) {
        int b   = pix / (OH * OW);
        int rem = pix - b * (OH * OW);
        int y   = rem / OW;
        int x   = rem - y * OW;

        // ================= Stage 1: build M_t^q into Ms[0..511] =================
        #pragma unroll
        for (int core = 0; core < 4; core++) {
            const int py = y + (core >> 1);
            const int px = x + (core & 1);
            const int base = ((b * H + py) * W + px) * 4;
            const float4 c0 = *(const float4*)(ch0 + base);
            const float4 c1 = *(const float4*)(ch1 + base);
            float v[16];
            v[0]  = c0.x * c1.x; v[1]  = c0.x * c1.y; v[2]  = c0.x * c1.z; v[3]  = c0.x * c1.w;
            v[4]  = c0.y * c1.x; v[5]  = c0.y * c1.y; v[6]  = c0.y * c1.z; v[7]  = c0.y * c1.w;
            v[8]  = c0.z * c1.x; v[9]  = c0.z * c1.y; v[10] = c0.z * c1.z; v[11] = c0.z * c1.w;
            v[12] = c0.w * c1.x; v[13] = c0.w * c1.y; v[14] = c0.w * c1.z; v[15] = c0.w * c1.w;
            #pragma unroll
            for (int q = 0; q < 2; q++) {
                const float2* cp = (const float2*)smem + (core * 2 + q) * 16 * 32 + lane;
                float acc0 = 0.f, acc1 = 0.f;
                #pragma unroll
                for (int ac = 0; ac < 16; ac++) {
                    float2 cc = cp[ac * 32];
                    acc0 += cc.x * v[ac];
                    acc1 += cc.y * v[ac];
                }
                ((float2*)(Ms + (core * 2 + q) * 64))[lane] = make_float2(acc0, acc1);
            }
        }
        __syncwarp();

        // ================= Stage 2a: A^{pq}[i,k] = sum_j M0^p[i,j] M1^q[j,k] ===
        float a[8];
        {
            const int p = hi >> 1, q = hi & 1;
            float rm0[8];
            float4 t0 = *(const float4*)(Ms + p * 64 + lo * 8);
            float4 t1 = *(const float4*)(Ms + p * 64 + lo * 8 + 4);
            rm0[0] = t0.x; rm0[1] = t0.y; rm0[2] = t0.z; rm0[3] = t0.w;
            rm0[4] = t1.x; rm0[5] = t1.y; rm0[6] = t1.z; rm0[7] = t1.w;
            #pragma unroll
            for (int k = 0; k < 8; k++) a[k] = 0.f;
            #pragma unroll
            for (int j = 0; j < 8; j++) {
                float4 r0 = *(const float4*)(Ms + (2 + q) * 64 + j * 8);
                float4 r1 = *(const float4*)(Ms + (2 + q) * 64 + j * 8 + 4);
                a[0] += rm0[j] * r0.x; a[1] += rm0[j] * r0.y;
                a[2] += rm0[j] * r0.z; a[3] += rm0[j] * r0.w;
                a[4] += rm0[j] * r1.x; a[5] += rm0[j] * r1.y;
                a[6] += rm0[j] * r1.z; a[7] += rm0[j] * r1.w;
            }
        }

        // ====== Stage 2b: Bt[rs][i][k] = B^{rs}[k][i] = sum_l M2^r[k,l] M3^s[l,i]
        float bb[8];
        {
            const int r = hi >> 1, s = hi & 1;
            float rm3[8];
            #pragma unroll
            for (int ll = 0; ll < 8; ll++) {          // rotated to avoid conflicts
                int l = (ll + hi) & 7;
                rm3[l] = Ms[(6 + s) * 64 + l * 8 + lo];
            }
            #pragma unroll
            for (int k = 0; k < 8; k++) {
                float4 m2a = *(const float4*)(Ms + (4 + r) * 64 + k * 8);
                float4 m2b = *(const float4*)(Ms + (4 + r) * 64 + k * 8 + 4);
                bb[k] = m2a.x * rm3[0] + m2a.y * rm3[1] + m2a.z * rm3[2] + m2a.w * rm3[3]
                      + m2b.x * rm3[4] + m2b.y * rm3[5] + m2b.z * rm3[6] + m2b.w * rm3[7];
            }
        }
        __syncwarp();

        // store A and Bt (blocks stride 68 floats to de-bank the final reads)
        *(float4*)(Ms + hi * 68 + lo * 8)           = make_float4(a[0], a[1], a[2], a[3]);
        *(float4*)(Ms + hi * 68 + lo * 8 + 4)       = make_float4(a[4], a[5], a[6], a[7]);
        *(float4*)(Ms + 288 + hi * 68 + lo * 8)     = make_float4(bb[0], bb[1], bb[2], bb[3]);
        *(float4*)(Ms + 288 + hi * 68 + lo * 8 + 4) = make_float4(bb[4], bb[5], bb[6], bb[7]);
        __syncwarp();

        // ================= Final: out[o] = <A[pq], Bt[rs]> (64-elem dot) =======
        {
            const int o = lane >> 1, half = lane & 1;   // o = pq*4 + rs = p*8+q*4+r*2+s
            const float4* Ab = (const float4*)(Ms + (o >> 2) * 68 + half * 32);
            const float4* Bb = (const float4*)(Ms + 288 + (o & 3) * 68 + half * 32);
            float sum = 0.f;
            #pragma unroll
            for (int t = 0; t < 8; t++) {
                float4 av = Ab[t];
                float4 bv = Bb[t];
                sum += av.x * bv.x + av.y * bv.y + av.z * bv.z + av.w * bv.w;
            }
            sum += __shfl_xor_sync(0xffffffffu, sum, 1);
            if (half == 0)
                out[pix * 16 + o] = sum;
        }
        __syncwarp();
    }
}

extern "C" void kernel_launch(void* const* d_in, const int* in_sizes, int n_in,
                              void* d_out, int out_size)
{
    const float* channels = (const float*)d_in[0];
    const float* cores    = (const float*)d_in[1];
    float* out            = (float*)d_out;

    static bool attr_set = false;
    if (!attr_set) {
        cudaFuncSetAttribute(convsbs_kernel,
                             cudaFuncAttributeMaxDynamicSharedMemorySize,
                             SMEM_F * sizeof(float));
        attr_set = true;
    }
    convsbs_kernel<<<NCTAS, 256, SMEM_F * sizeof(float)>>>(channels, cores, out);
}

// round 2
// speedup vs baseline: 1.4883x; 1.4883x over previous
#include <cuda_runtime.h>

// ConvSBS: fused 2-stage tensor-network contraction.
// channels: [2, 8, 128, 128, 4] f32   (ch0, ch1)
// cores:    [4, 2, 8, 8, 4, 4] f32    ([t, q, l, r, a, c]), t at (h,w)=(t>>1,t&1)
// out:      [8, 127, 127, 16] f32
//
// out[b,y,x, p*8+q*4+r*2+s] = sum_{ijkl} M0^p[i,j] M1^q[j,k] M2^r[k,l] M3^s[l,i]
// M_t^q[l,r] = sum_{a,c} core[t,q,l,r,a,c] * ch0[b,y+ht,x+wt,a] * ch1[b,y+ht,x+wt,c]

#define BATCH 8
#define H 128
#define W 128
#define OH 127
#define OW 127
#define PAIRS_PER_ROW 64                    // pair j covers x = 2j, 2j+1 (2j+1 may be invalid at j=63)
#define TOT_PAIRS (BATCH * OH * PAIRS_PER_ROW)

#define WARPS_PER_CTA 8
#define NCTAS 592

// smem (floats):
//   [0, 8192)            : cores relayout [t*2+q][a*4+c][l*8+r]   (32 KB)
//   per-warp (1024 floats = 4 KB):
//     pixel A: M blocks 0..5 at [0,384), MT3[s] at [384+s*64, ..512)
//     pixel B: same layout at +512
#define CORES_F 8192
#define WARP_F  1024
#define SMEM_F  (CORES_F + WARPS_PER_CTA * WARP_F)

__global__ void __launch_bounds__(256) convsbs_kernel(
    const float* __restrict__ channels,
    const float* __restrict__ cores,
    float* __restrict__ out)
{
    extern __shared__ float smem[];
    const int tid = threadIdx.x;

    // ---- relayout cores: [t][q][l][r][a][c] -> [t*2+q][a*4+c][l*8+r] ----
    for (int idx = tid; idx < 8192; idx += blockDim.x) {
        int c = idx & 3;
        int a = (idx >> 2) & 3;
        int r = (idx >> 4) & 7;
        int l = (idx >> 7) & 7;
        int q = (idx >> 10) & 1;
        int t = idx >> 11;
        smem[(((t * 2 + q) * 16 + (a * 4 + c)) << 6) + (l * 8 + r)] = cores[idx];
    }
    __syncthreads();

    const int warp = tid >> 5;
    const int lane = tid & 31;
    float* Ms = smem + CORES_F + warp * WARP_F;

    const float* __restrict__ ch0 = channels;
    const float* __restrict__ ch1 = channels + BATCH * H * W * 4;

    const int nwarps = gridDim.x * WARPS_PER_CTA;
    const int hi = lane >> 3;   // pq (A stage) / rs (B stage)
    const int lo = lane & 7;    // row index i within the 8x8 blocks

    for (int pr = blockIdx.x * WARPS_PER_CTA + warp; pr < TOT_PAIRS; pr += nwarps) {
        int b   = pr / (OH * PAIRS_PER_ROW);
        int rem = pr - b * (OH * PAIRS_PER_ROW);
        int y   = rem / PAIRS_PER_ROW;
        int x0  = (rem - y * PAIRS_PER_ROW) * 2;
        const bool p1valid = (x0 + 1 < OW);

        // ============ Stage 1: M_t^q for pixels x0 (A) and x0+1 (B) ============
        #pragma unroll
        for (int t = 0; t < 4; t++) {
            const int py  = y + (t >> 1);
            const int pxA = x0 + (t & 1);
            const int pxB = min(pxA + 1, W - 1);
            const int baseA = ((b * H + py) * W + pxA) * 4;
            const int baseB = ((b * H + py) * W + pxB) * 4;
            const float4 a0 = *(const float4*)(ch0 + baseA);
            const float4 a1 = *(const float4*)(ch1 + baseA);
            const float4 b0 = *(const float4*)(ch0 + baseB);
            const float4 b1 = *(const float4*)(ch1 + baseB);
            float vA[16], vB[16];
            vA[0]=a0.x*a1.x; vA[1]=a0.x*a1.y; vA[2]=a0.x*a1.z; vA[3]=a0.x*a1.w;
            vA[4]=a0.y*a1.x; vA[5]=a0.y*a1.y; vA[6]=a0.y*a1.z; vA[7]=a0.y*a1.w;
            vA[8]=a0.z*a1.x; vA[9]=a0.z*a1.y; vA[10]=a0.z*a1.z; vA[11]=a0.z*a1.w;
            vA[12]=a0.w*a1.x; vA[13]=a0.w*a1.y; vA[14]=a0.w*a1.z; vA[15]=a0.w*a1.w;
            vB[0]=b0.x*b1.x; vB[1]=b0.x*b1.y; vB[2]=b0.x*b1.z; vB[3]=b0.x*b1.w;
            vB[4]=b0.y*b1.x; vB[5]=b0.y*b1.y; vB[6]=b0.y*b1.z; vB[7]=b0.y*b1.w;
            vB[8]=b0.z*b1.x; vB[9]=b0.z*b1.y; vB[10]=b0.z*b1.z; vB[11]=b0.z*b1.w;
            vB[12]=b0.w*b1.x; vB[13]=b0.w*b1.y; vB[14]=b0.w*b1.z; vB[15]=b0.w*b1.w;

            #pragma unroll
            for (int q = 0; q < 2; q++) {
                const float2* cp = (const float2*)smem + (t * 2 + q) * 512 + lane;
                float accA0 = 0.f, accA1 = 0.f, accB0 = 0.f, accB1 = 0.f;
                #pragma unroll
                for (int ac = 0; ac < 16; ac++) {
                    float2 cc = cp[ac * 32];
                    accA0 += cc.x * vA[ac];
                    accA1 += cc.y * vA[ac];
                    accB0 += cc.x * vB[ac];
                    accB1 += cc.y * vB[ac];
                }
                if (t < 3) {
                    ((float2*)(Ms + (t * 2 + q) * 64))[lane]       = make_float2(accA0, accA1);
                    ((float2*)(Ms + 512 + (t * 2 + q) * 64))[lane] = make_float2(accB0, accB1);
                } else {
                    // M3: store transposed only (MT3[s][r*8+l] = M3^s[l,r])
                    const int i0 = 2 * lane, i1 = 2 * lane + 1;
                    const int ta0 = (i0 & 7) * 8 + (i0 >> 3);
                    const int ta1 = (i1 & 7) * 8 + (i1 >> 3);
                    Ms[384 + q * 64 + ta0]       = accA0;
                    Ms[384 + q * 64 + ta1]       = accA1;
                    Ms[512 + 384 + q * 64 + ta0] = accB0;
                    Ms[512 + 384 + q * 64 + ta1] = accB1;
                }
            }
        }
        __syncwarp();

        // ============ Stage 2 + final, per pixel ============
        #pragma unroll
        for (int pp = 0; pp < 2; pp++) {
            if (pp == 1 && !p1valid) break;   // warp-uniform
            const float* M = Ms + pp * 512;

            // ---- A^{pq}[lo, k] = sum_j M0^p[lo,j] M1^q[j,k],  pq = hi ----
            float a[8];
            {
                const int p = hi >> 1, q = hi & 1;
                float rm0[8];
                float4 t0 = *(const float4*)(M + p * 64 + lo * 8);
                float4 t1 = *(const float4*)(M + p * 64 + lo * 8 + 4);
                rm0[0]=t0.x; rm0[1]=t0.y; rm0[2]=t0.z; rm0[3]=t0.w;
                rm0[4]=t1.x; rm0[5]=t1.y; rm0[6]=t1.z; rm0[7]=t1.w;
                #pragma unroll
                for (int k = 0; k < 8; k++) a[k] = 0.f;
                #pragma unroll
                for (int j = 0; j < 8; j++) {
                    float4 r0 = *(const float4*)(M + (2 + q) * 64 + j * 8);
                    float4 r1 = *(const float4*)(M + (2 + q) * 64 + j * 8 + 4);
                    a[0] += rm0[j] * r0.x; a[1] += rm0[j] * r0.y;
                    a[2] += rm0[j] * r0.z; a[3] += rm0[j] * r0.w;
                    a[4] += rm0[j] * r1.x; a[5] += rm0[j] * r1.y;
                    a[6] += rm0[j] * r1.z; a[7] += rm0[j] * r1.w;
                }
            }

            // ---- Bt[rs][lo, k] = B^{rs}[k, lo] = sum_l M2^r[k,l] M3^s[l, lo] ----
            float bbv[8];
            {
                const int r = hi >> 1, s = hi & 1;
                float rm3[8];
                float4 t0 = *(const float4*)(M + 384 + s * 64 + lo * 8);      // MT3 row lo
                float4 t1 = *(const float4*)(M + 384 + s * 64 + lo * 8 + 4);
                rm3[0]=t0.x; rm3[1]=t0.y; rm3[2]=t0.z; rm3[3]=t0.w;
                rm3[4]=t1.x; rm3[5]=t1.y; rm3[6]=t1.z; rm3[7]=t1.w;
                #pragma unroll
                for (int k = 0; k < 8; k++) {
                    float4 m2a = *(const float4*)(M + (4 + r) * 64 + k * 8);
                    float4 m2b = *(const float4*)(M + (4 + r) * 64 + k * 8 + 4);
                    bbv[k] = m2a.x*rm3[0] + m2a.y*rm3[1] + m2a.z*rm3[2] + m2a.w*rm3[3]
                           + m2b.x*rm3[4] + m2b.y*rm3[5] + m2b.z*rm3[6] + m2b.w*rm3[7];
                }
            }

            // ---- final: out[pq*4+rs] = sum_{lo,k} A^{pq}[lo,k] Bt[rs][lo,k] ----
            float partial[4] = {0.f, 0.f, 0.f, 0.f};
            #pragma unroll
            for (int rs = 0; rs < 4; rs++) {
                const int src = rs * 8 + lo;
                #pragma unroll
                for (int k = 0; k < 8; k++) {
                    float bv = __shfl_sync(0xffffffffu, bbv[k], src);
                    partial[rs] += a[k] * bv;
                }
            }
            #pragma unroll
            for (int m = 1; m <= 4; m <<= 1) {
                #pragma unroll
                for (int rs = 0; rs < 4; rs++)
                    partial[rs] += __shfl_xor_sync(0xffffffffu, partial[rs], m);
            }
            if (lo == 0) {
                const int pix = (b * OH + y) * OW + (x0 + pp);
                *(float4*)(out + pix * 16 + hi * 4) =
                    make_float4(partial[0], partial[1], partial[2], partial[3]);
            }
        }
        __syncwarp();
    }
}

extern "C" void kernel_launch(void* const* d_in, const int* in_sizes, int n_in,
                              void* d_out, int out_size)
{
    const float* channels = (const float*)d_in[0];
    const float* cores    = (const float*)d_in[1];
    float* out            = (float*)d_out;

    static bool attr_set = false;
    if (!attr_set) {
        cudaFuncSetAttribute(convsbs_kernel,
                             cudaFuncAttributeMaxDynamicSharedMemorySize,
                             SMEM_F * sizeof(float));
        attr_set = true;
    }
    convsbs_kernel<<<NCTAS, 256, SMEM_F * sizeof(float)>>>(channels, cores, out);
}

// round 3
// speedup vs baseline: 1.6985x; 1.1412x over previous
#include <cuda_runtime.h>

// ConvSBS fused contraction, pixel-pair SIMD via f32x2 packed math.
// channels: [2, 8, 128, 128, 4] f32 ; cores: [4, 2, 8, 8, 4, 4] f32 ; out: [8,127,127,16] f32

typedef unsigned long long ull;

__device__ __forceinline__ ull pk2(float lo, float hi) {
    ull d; asm("mov.b64 %0, {%1, %2};" : "=l"(d) : "f"(lo), "f"(hi)); return d;
}
__device__ __forceinline__ float2 up2(ull v) {
    float2 r; asm("mov.b64 {%0, %1}, %2;" : "=f"(r.x), "=f"(r.y) : "l"(v)); return r;
}
__device__ __forceinline__ ull fma2(ull a, ull b, ull c) {
    ull d; asm("fma.rn.f32x2 %0, %1, %2, %3;" : "=l"(d) : "l"(a), "l"(b), "l"(c)); return d;
}
__device__ __forceinline__ ull mul2(ull a, ull b) {
    ull d; asm("mul.rn.f32x2 %0, %1, %2;" : "=l"(d) : "l"(a), "l"(b)); return d;
}
__device__ __forceinline__ ull add2(ull a, ull b) {
    ull d; asm("add.rn.f32x2 %0, %1, %2;" : "=l"(d) : "l"(a), "l"(b)); return d;
}

#define BATCH 8
#define H 128
#define W 128
#define OH 127
#define OW 127
#define GX 32                              // groups of 4 px per row
#define TOT_GROUPS (BATCH * OH * GX)       // 32512

#define WARPS_PER_CTA 8
#define NCTAS 296                          // 2 CTAs/SM * 148

// smem floats: [0,8192) cores [t*2+q][a*4+c][l*8+r]; per warp 2048 floats (2 pair-M buffers).
// Pair-M buffer: 8 blocks * 64 float2 (each float2 = (px0,px1) value of M[l*8+r]).
#define CORES_F 8192
#define WARP_F  2048
#define SMEM_F  (CORES_F + WARPS_PER_CTA * WARP_F)

__global__ void __launch_bounds__(256, 2) convsbs_kernel(
    const float* __restrict__ channels,
    const float* __restrict__ cores,
    float* __restrict__ out)
{
    extern __shared__ float smem[];
    const int tid = threadIdx.x;

    // cores relayout: [t][q][l][r][a][c] -> [t*2+q][a*4+c][l*8+r]
    for (int idx = tid; idx < 8192; idx += blockDim.x) {
        int c = idx & 3, a = (idx >> 2) & 3, r = (idx >> 4) & 7;
        int l = (idx >> 7) & 7, q = (idx >> 10) & 1, t = idx >> 11;
        smem[(((t * 2 + q) * 16 + (a * 4 + c)) << 6) + (l * 8 + r)] = cores[idx];
    }
    __syncthreads();

    const int warp = tid >> 5;
    const int lane = tid & 31;
    const int hi = lane >> 3;    // pq (A) / rs (B) selector
    const int lo = lane & 7;     // row index
    float* Wb = smem + CORES_F + warp * WARP_F;

    const float* __restrict__ ch0 = channels;
    const float* __restrict__ ch1 = channels + BATCH * H * W * 4;
    const ull z = pk2(0.f, 0.f);
    const int nwork = gridDim.x * WARPS_PER_CTA;

    for (int g = blockIdx.x * WARPS_PER_CTA + warp; g < TOT_GROUPS; g += nwork) {
        int b   = g / (OH * GX);
        int rem = g - b * (OH * GX);
        int y   = rem >> 5;
        int x0  = (rem & 31) << 2;          // group covers out-x x0..x0+3

        // ========== Stage 1: M for pairs A=(x0,x0+1), B=(x0+2,x0+3) ==========
        #pragma unroll
        for (int t = 0; t < 4; t++) {
            const int py  = y + (t >> 1);
            const int cxb = x0 + (t & 1);
            float4 c0[4], c1[4];
            #pragma unroll
            for (int d = 0; d < 4; d++) {
                int cx = min(cxb + d, W - 1);
                int base = ((b * H + py) * W + cx) * 4;
                c0[d] = *(const float4*)(ch0 + base);
                c1[d] = *(const float4*)(ch1 + base);
            }
            // packed channels per pair
            ull c0A[4], c1A[4], c0B[4], c1B[4];
            c0A[0]=pk2(c0[0].x,c0[1].x); c0A[1]=pk2(c0[0].y,c0[1].y);
            c0A[2]=pk2(c0[0].z,c0[1].z); c0A[3]=pk2(c0[0].w,c0[1].w);
            c1A[0]=pk2(c1[0].x,c1[1].x); c1A[1]=pk2(c1[0].y,c1[1].y);
            c1A[2]=pk2(c1[0].z,c1[1].z); c1A[3]=pk2(c1[0].w,c1[1].w);
            c0B[0]=pk2(c0[2].x,c0[3].x); c0B[1]=pk2(c0[2].y,c0[3].y);
            c0B[2]=pk2(c0[2].z,c0[3].z); c0B[3]=pk2(c0[2].w,c0[3].w);
            c1B[0]=pk2(c1[2].x,c1[3].x); c1B[1]=pk2(c1[2].y,c1[3].y);
            c1B[2]=pk2(c1[2].z,c1[3].z); c1B[3]=pk2(c1[2].w,c1[3].w);

            ull vA[16], vB[16];
            #pragma unroll
            for (int a = 0; a < 4; a++)
                #pragma unroll
                for (int c = 0; c < 4; c++) {
                    vA[a * 4 + c] = mul2(c0A[a], c1A[c]);
                    vB[a * 4 + c] = mul2(c0B[a], c1B[c]);
                }

            #pragma unroll
            for (int q = 0; q < 2; q++) {
                const int bi = t * 2 + q;
                const float2* cp = (const float2*)smem + bi * 512 + lane;
                ull aA0 = z, aA1 = z, aB0 = z, aB1 = z;
                #pragma unroll
                for (int ac = 0; ac < 16; ac++) {
                    float2 cc = cp[ac * 32];
                    ull cx2 = pk2(cc.x, cc.x);
                    ull cy2 = pk2(cc.y, cc.y);
                    aA0 = fma2(cx2, vA[ac], aA0);
                    aA1 = fma2(cy2, vA[ac], aA1);
                    aB0 = fma2(cx2, vB[ac], aB0);
                    aB1 = fma2(cy2, vB[ac], aB1);
                }
                float2 u0 = up2(aA0), u1 = up2(aA1), u2 = up2(aB0), u3 = up2(aB1);
                ((float4*)Wb)[bi * 32 + lane]       = make_float4(u0.x, u0.y, u1.x, u1.y);
                ((float4*)(Wb + 1024))[bi * 32 + lane] = make_float4(u2.x, u2.y, u3.x, u3.y);
            }
        }
        __syncwarp();

        // ========== Stage 2 per pair (everything f32x2 over the pixel pair) ==
        #pragma unroll
        for (int pp = 0; pp < 2; pp++) {
            float* M = Wb + pp * 1024;
            const float4* M4 = (const float4*)M;
            const float2* M2 = (const float2*)M;
            const int p = hi >> 1, q = hi & 1;   // also r, s for the B stage

            // A2^{pq}[lo, k] = sum_j M0[lo,j] (x) M1[j,k]
            ull rm0[8];
            #pragma unroll
            for (int h = 0; h < 4; h++) {
                float4 u = M4[p * 32 + lo * 4 + h];
                rm0[2 * h]     = pk2(u.x, u.y);
                rm0[2 * h + 1] = pk2(u.z, u.w);
            }
            ull a2[8];
            #pragma unroll
            for (int k = 0; k < 8; k++) a2[k] = z;
            #pragma unroll
            for (int j = 0; j < 8; j++) {
                ull m[8];
                #pragma unroll
                for (int h = 0; h < 4; h++) {
                    float4 u = M4[(2 + q) * 32 + j * 4 + h];
                    m[2 * h]     = pk2(u.x, u.y);
                    m[2 * h + 1] = pk2(u.z, u.w);
                }
                #pragma unroll
                for (int k = 0; k < 8; k++) a2[k] = fma2(rm0[j], m[k], a2[k]);
            }

            // bb[k] = B2^{rs}[k, lo] = sum_l M2[k,l] (x) M3[l,lo]
            ull rm3[8];
            #pragma unroll
            for (int l = 0; l < 8; l++) {
                float2 e = M2[(6 + q) * 64 + l * 8 + lo];
                rm3[l] = pk2(e.x, e.y);
            }
            ull bb[8];
            #pragma unroll
            for (int k = 0; k < 8; k++) {
                ull acc = z;
                #pragma unroll
                for (int h = 0; h < 4; h++) {
                    float4 u = M4[(4 + p) * 32 + k * 4 + h];
                    acc = fma2(pk2(u.x, u.y), rm3[2 * h], acc);
                    acc = fma2(pk2(u.z, u.w), rm3[2 * h + 1], acc);
                }
                bb[k] = acc;
            }
            __syncwarp();

            // exchange B through smem, k-major (overwrites this pair's M blocks 0..3)
            float2* BT = (float2*)M;
            #pragma unroll
            for (int k = 0; k < 8; k++) BT[k * 32 + lane] = up2(bb[k]);
            __syncwarp();

            // out2[hi*4+rs] = sum_{lo,k} A2[lo,k] (x) B2[k,lo]
            ull part[4];
            #pragma unroll
            for (int rs = 0; rs < 4; rs++) {
                ull acc = z;
                #pragma unroll
                for (int k = 0; k < 8; k++) {
                    float2 e = BT[k * 32 + rs * 8 + lo];
                    acc = fma2(a2[k], pk2(e.x, e.y), acc);
                }
                part[rs] = acc;
            }
            #pragma unroll
            for (int m = 1; m <= 4; m <<= 1)
                #pragma unroll
                for (int rs = 0; rs < 4; rs++)
                    part[rs] = add2(part[rs], __shfl_xor_sync(0xffffffffu, part[rs], m));

            if (lo == 0) {
                const int xx = x0 + pp * 2;
                float2 P0 = up2(part[0]), P1 = up2(part[1]);
                float2 P2 = up2(part[2]), P3 = up2(part[3]);
                const int pix0 = (b * OH + y) * OW + xx;
                *(float4*)(out + pix0 * 16 + hi * 4) = make_float4(P0.x, P1.x, P2.x, P3.x);
                if (xx + 1 < OW)
                    *(float4*)(out + (pix0 + 1) * 16 + hi * 4) = make_float4(P0.y, P1.y, P2.y, P3.y);
            }
            __syncwarp();
        }
    }
}

extern "C" void kernel_launch(void* const* d_in, const int* in_sizes, int n_in,
                              void* d_out, int out_size)
{
    const float* channels = (const float*)d_in[0];
    const float* cores    = (const float*)d_in[1];
    float* out            = (float*)d_out;

    static bool attr_set = false;
    if (!attr_set) {
        cudaFuncSetAttribute(convsbs_kernel,
                             cudaFuncAttributeMaxDynamicSharedMemorySize,
                             SMEM_F * sizeof(float));
        attr_set = true;
    }
    convsbs_kernel<<<NCTAS, 256, SMEM_F * sizeof(float)>>>(channels, cores, out);
}

// round 5
// speedup vs baseline: 2.0888x; 1.2298x over previous
#include <cuda_runtime.h>

// ConvSBS fused contraction, pixel-pair SIMD (f32x2), restructured stage 2.
// channels: [2, 8, 128, 128, 4] f32 ; cores: [4, 2, 8, 8, 4, 4] f32 ; out: [8,127,127,16] f32

typedef unsigned long long ull;

__device__ __forceinline__ ull pk2(float lo, float hi) {
    ull d; asm("mov.b64 %0, {%1, %2};" : "=l"(d) : "f"(lo), "f"(hi)); return d;
}
__device__ __forceinline__ float2 up2(ull v) {
    float2 r; asm("mov.b64 {%0, %1}, %2;" : "=f"(r.x), "=f"(r.y) : "l"(v)); return r;
}
__device__ __forceinline__ ull fma2(ull a, ull b, ull c) {
    ull d; asm("fma.rn.f32x2 %0, %1, %2, %3;" : "=l"(d) : "l"(a), "l"(b), "l"(c)); return d;
}
__device__ __forceinline__ ull mul2(ull a, ull b) {
    ull d; asm("mul.rn.f32x2 %0, %1, %2;" : "=l"(d) : "l"(a), "l"(b)); return d;
}
__device__ __forceinline__ ull add2(ull a, ull b) {
    ull d; asm("add.rn.f32x2 %0, %1, %2;" : "=l"(d) : "l"(a), "l"(b)); return d;
}

#define BATCH 8
#define H 128
#define W 128
#define OH 127
#define OW 127
#define GX 32
#define TOT_GROUPS (BATCH * OH * GX)

#define WARPS_PER_CTA 7
#define NTHREADS (WARPS_PER_CTA * 32)
#define NCTAS 296

// Per-pair scratch buffer: 640 ull (1280 floats).
//   M element (block bi, row, col) at ull idx bi*80 + row*10 + col   (bi=t*2+q, 8 blocks)
//   Overlay after M blocks 0..3 are consumed:
//     Bsm[rs][k][i] at rs*82 + k*10 + i          (max 323; clobbers blocks 0..4 partially - safe)
//     Psm[q][i][o8] at 336 + (q*8+i)*10 + q*8 + o8  (max 501)
#define PAIR_ULL 640
#define WARP_ULL (2 * PAIR_ULL)
#define CORES_F 8192
#define SMEM_F  (CORES_F + WARPS_PER_CTA * WARP_ULL * 2)

__global__ void __launch_bounds__(NTHREADS, 2) convsbs_kernel(
    const float* __restrict__ channels,
    const float* __restrict__ cores,
    float* __restrict__ out)
{
    extern __shared__ float smem[];
    const int tid = threadIdx.x;

    // cores relayout: [t][q][l][r][a][c] -> [t*2+q][a*4+c][l*8+r]
    for (int idx = tid; idx < 8192; idx += NTHREADS) {
        int c = idx & 3, a = (idx >> 2) & 3, r = (idx >> 4) & 7;
        int l = (idx >> 7) & 7, q = (idx >> 10) & 1, t = idx >> 11;
        smem[(((t * 2 + q) * 16 + (a * 4 + c)) << 6) + (l * 8 + r)] = cores[idx];
    }
    __syncthreads();

    const int warp = tid >> 5;
    const int lane = tid & 31;
    ull* Wb = (ull*)(smem + CORES_F) + warp * WARP_ULL;

    const int g2 = lane >> 4;        // q (A-stage) / s (B-stage) / q (final)
    const int i2 = (lane >> 1) & 7;  // i (A) / k (B) / i (final)
    const int h2 = lane & 1;         // k-half (A) / i-half (B)

    const float* __restrict__ ch0 = channels;
    const float* __restrict__ ch1 = channels + BATCH * H * W * 4;
    const ull z = pk2(0.f, 0.f);
    const int nwork = gridDim.x * WARPS_PER_CTA;

    for (int g = blockIdx.x * WARPS_PER_CTA + warp; g < TOT_GROUPS; g += nwork) {
        int b   = g / (OH * GX);
        int rem = g - b * (OH * GX);
        int y   = rem >> 5;
        int x0  = (rem & 31) << 2;

        // ========== Stage 1: M for pairs A=(x0,x0+1), B=(x0+2,x0+3) ==========
        #pragma unroll
        for (int t = 0; t < 4; t++) {
            const int py  = y + (t >> 1);
            const int cxb = x0 + (t & 1);
            float4 c0[4], c1[4];
            #pragma unroll
            for (int d = 0; d < 4; d++) {
                int cx = min(cxb + d, W - 1);
                int base = ((b * H + py) * W + cx) * 4;
                c0[d] = *(const float4*)(ch0 + base);
                c1[d] = *(const float4*)(ch1 + base);
            }
            ull c0A[4], c1A[4], c0B[4], c1B[4];
            c0A[0]=pk2(c0[0].x,c0[1].x); c0A[1]=pk2(c0[0].y,c0[1].y);
            c0A[2]=pk2(c0[0].z,c0[1].z); c0A[3]=pk2(c0[0].w,c0[1].w);
            c1A[0]=pk2(c1[0].x,c1[1].x); c1A[1]=pk2(c1[0].y,c1[1].y);
            c1A[2]=pk2(c1[0].z,c1[1].z); c1A[3]=pk2(c1[0].w,c1[1].w);
            c0B[0]=pk2(c0[2].x,c0[3].x); c0B[1]=pk2(c0[2].y,c0[3].y);
            c0B[2]=pk2(c0[2].z,c0[3].z); c0B[3]=pk2(c0[2].w,c0[3].w);
            c1B[0]=pk2(c1[2].x,c1[3].x); c1B[1]=pk2(c1[2].y,c1[3].y);
            c1B[2]=pk2(c1[2].z,c1[3].z); c1B[3]=pk2(c1[2].w,c1[3].w);

            ull vA[16], vB[16];
            #pragma unroll
            for (int a = 0; a < 4; a++)
                #pragma unroll
                for (int c = 0; c < 4; c++) {
                    vA[a * 4 + c] = mul2(c0A[a], c1A[c]);
                    vB[a * 4 + c] = mul2(c0B[a], c1B[c]);
                }

            const int row = lane >> 2;        // l of entry lr = 2*lane
            const int col = 2 * (lane & 3);   // r of entry lr = 2*lane
            #pragma unroll
            for (int q = 0; q < 2; q++) {
                const int bi = t * 2 + q;
                const float2* cp = (const float2*)smem + bi * 512 + lane;
                ull aA0 = z, aA1 = z, aB0 = z, aB1 = z;
                #pragma unroll
                for (int ac = 0; ac < 16; ac++) {
                    float2 cc = cp[ac * 32];
                    ull cx2 = pk2(cc.x, cc.x);
                    ull cy2 = pk2(cc.y, cc.y);
                    aA0 = fma2(cx2, vA[ac], aA0);
                    aA1 = fma2(cy2, vA[ac], aA1);
                    aB0 = fma2(cx2, vB[ac], aB0);
                    aB1 = fma2(cy2, vB[ac], aB1);
                }
                const int midx = bi * 80 + row * 10 + col;
                *(ulonglong2*)(Wb + midx)            = make_ulonglong2(aA0, aA1);
                *(ulonglong2*)(Wb + PAIR_ULL + midx) = make_ulonglong2(aB0, aB1);
            }
        }
        __syncwarp();

        // ========== Stage 2 per pair ==========
        #pragma unroll
        for (int pr = 0; pr < 2; pr++) {
            ull* M = Wb + pr * PAIR_ULL;

            // ---- A-stage: lane (q=g2, i=i2, kh=h2), both p accumulated ----
            // a2[p][kk] = A^{p,g2}[i2, h2*4+kk]
            ull a2[2][4];
            {
                ull rm0[2][8];
                #pragma unroll
                for (int p = 0; p < 2; p++) {
                    #pragma unroll
                    for (int c = 0; c < 4; c++) {
                        ulonglong2 u = *(const ulonglong2*)(M + p * 80 + i2 * 10 + 2 * c);
                        rm0[p][2 * c] = u.x; rm0[p][2 * c + 1] = u.y;
                    }
                }
                #pragma unroll
                for (int p = 0; p < 2; p++)
                    #pragma unroll
                    for (int kk = 0; kk < 4; kk++) a2[p][kk] = z;
                #pragma unroll
                for (int j = 0; j < 8; j++) {
                    ulonglong2 m1a = *(const ulonglong2*)(M + (2 + g2) * 80 + j * 10 + h2 * 4);
                    ulonglong2 m1b = *(const ulonglong2*)(M + (2 + g2) * 80 + j * 10 + h2 * 4 + 2);
                    #pragma unroll
                    for (int p = 0; p < 2; p++) {
                        a2[p][0] = fma2(rm0[p][j], m1a.x, a2[p][0]);
                        a2[p][1] = fma2(rm0[p][j], m1a.y, a2[p][1]);
                        a2[p][2] = fma2(rm0[p][j], m1b.x, a2[p][2]);
                        a2[p][3] = fma2(rm0[p][j], m1b.y, a2[p][3]);
                    }
                }
            }

            // ---- B-stage: lane (s=g2, k=i2, ih=h2), both r accumulated ----
            // bt[r][ii] = B^{r,g2}[i2, h2*4+ii] = sum_l M2^r[i2,l] * M3^{g2}[l, h2*4+ii]
            ull bt[2][4];
            {
                ull rm2[2][8];
                #pragma unroll
                for (int r = 0; r < 2; r++) {
                    #pragma unroll
                    for (int c = 0; c < 4; c++) {
                        ulonglong2 u = *(const ulonglong2*)(M + (4 + r) * 80 + i2 * 10 + 2 * c);
                        rm2[r][2 * c] = u.x; rm2[r][2 * c + 1] = u.y;
                    }
                }
                #pragma unroll
                for (int r = 0; r < 2; r++)
                    #pragma unroll
                    for (int ii = 0; ii < 4; ii++) bt[r][ii] = z;
                #pragma unroll
                for (int l = 0; l < 8; l++) {
                    ulonglong2 m3a = *(const ulonglong2*)(M + (6 + g2) * 80 + l * 10 + h2 * 4);
                    ulonglong2 m3b = *(const ulonglong2*)(M + (6 + g2) * 80 + l * 10 + h2 * 4 + 2);
                    #pragma unroll
                    for (int r = 0; r < 2; r++) {
                        bt[r][0] = fma2(rm2[r][l], m3a.x, bt[r][0]);
                        bt[r][1] = fma2(rm2[r][l], m3a.y, bt[r][1]);
                        bt[r][2] = fma2(rm2[r][l], m3b.x, bt[r][2]);
                        bt[r][3] = fma2(rm2[r][l], m3b.y, bt[r][3]);
                    }
                }
            }
            __syncwarp();

            // ---- store B: Bsm[rs][k][i] at rs*82 + k*10 + i  (rs = r*2 + s) ----
            #pragma unroll
            for (int r = 0; r < 2; r++) {
                const int base = (r * 2 + g2) * 82 + i2 * 10 + h2 * 4;
                *(ulonglong2*)(M + base)     = make_ulonglong2(bt[r][0], bt[r][1]);
                *(ulonglong2*)(M + base + 2) = make_ulonglong2(bt[r][2], bt[r][3]);
            }
            __syncwarp();

            // ---- final partials at lane (q=g2, i=i2, kh=h2) ----
            ull part[2][4];
            #pragma unroll
            for (int p = 0; p < 2; p++)
                #pragma unroll
                for (int rs = 0; rs < 4; rs++) part[p][rs] = z;
            #pragma unroll
            for (int rs = 0; rs < 4; rs++) {
                #pragma unroll
                for (int kk = 0; kk < 4; kk++) {
                    ull Bv = M[rs * 82 + (h2 * 4 + kk) * 10 + i2];
                    part[0][rs] = fma2(a2[0][kk], Bv, part[0][rs]);
                    part[1][rs] = fma2(a2[1][kk], Bv, part[1][rs]);
                }
            }
            // reduce over kh (lane bit 0)
            #pragma unroll
            for (int p = 0; p < 2; p++)
                #pragma unroll
                for (int rs = 0; rs < 4; rs++)
                    part[p][rs] = add2(part[p][rs],
                                       __shfl_xor_sync(0xffffffffu, part[p][rs], 1));
            // Psm[q][i][p*4+rs] at 336 + (q*8+i)*10 + q*8 + (p*4+rs)
            if (h2 == 0) {
                const int pbase = 336 + (g2 * 8 + i2) * 10 + g2 * 8;
                *(ulonglong2*)(M + pbase)     = make_ulonglong2(part[0][0], part[0][1]);
                *(ulonglong2*)(M + pbase + 2) = make_ulonglong2(part[0][2], part[0][3]);
                *(ulonglong2*)(M + pbase + 4) = make_ulonglong2(part[1][0], part[1][1]);
                *(ulonglong2*)(M + pbase + 6) = make_ulonglong2(part[1][2], part[1][3]);
            }
            __syncwarp();

            // ---- output: lanes 0..15, q=lane>>3, o8=lane&7 (p=o8>>2, rs=o8&3) ----
            if (lane < 16) {
                const int q = lane >> 3, o8 = lane & 7;
                ull s = z;
                #pragma unroll
                for (int i = 0; i < 8; i++)
                    s = add2(s, M[336 + (q * 8 + i) * 10 + q * 8 + o8]);
                const int p = o8 >> 2, rs = o8 & 3;
                const int outIdx = p * 8 + q * 4 + rs;
                const int xx = x0 + pr * 2;
                const int pix0 = (b * OH + y) * OW + xx;
                float2 pv = up2(s);
                out[pix0 * 16 + outIdx] = pv.x;
                if (xx + 1 < OW)
                    out[(pix0 + 1) * 16 + outIdx] = pv.y;
            }
            __syncwarp();
        }
    }
}

extern "C" void kernel_launch(void* const* d_in, const int* in_sizes, int n_in,
                              void* d_out, int out_size)
{
    const float* channels = (const float*)d_in[0];
    const float* cores    = (const float*)d_in[1];
    float* out            = (float*)d_out;

    static bool attr_set = false;
    if (!attr_set) {
        cudaFuncSetAttribute(convsbs_kernel,
                             cudaFuncAttributeMaxDynamicSharedMemorySize,
                             SMEM_F * sizeof(float));
        attr_set = true;
    }
    convsbs_kernel<<<NCTAS, NTHREADS, SMEM_F * sizeof(float)>>>(channels, cores, out);
}

// round 6
// speedup vs baseline: 2.1975x; 1.0520x over previous
#include <cuda_runtime.h>

// ConvSBS fused contraction, pixel-pair SIMD (f32x2).
// channels: [2, 8, 128, 128, 4] f32 ; cores: [4, 2, 8, 8, 4, 4] f32 ; out: [8,127,127,16] f32

typedef unsigned long long ull;

__device__ __forceinline__ ull pk2(float lo, float hi) {
    ull d; asm("mov.b64 %0, {%1, %2};" : "=l"(d) : "f"(lo), "f"(hi)); return d;
}
__device__ __forceinline__ float2 up2(ull v) {
    float2 r; asm("mov.b64 {%0, %1}, %2;" : "=f"(r.x), "=f"(r.y) : "l"(v)); return r;
}
__device__ __forceinline__ ull fma2(ull a, ull b, ull c) {
    ull d; asm("fma.rn.f32x2 %0, %1, %2, %3;" : "=l"(d) : "l"(a), "l"(b), "l"(c)); return d;
}
__device__ __forceinline__ ull mul2(ull a, ull b) {
    ull d; asm("mul.rn.f32x2 %0, %1, %2;" : "=l"(d) : "l"(a), "l"(b)); return d;
}
__device__ __forceinline__ ull add2(ull a, ull b) {
    ull d; asm("add.rn.f32x2 %0, %1, %2;" : "=l"(d) : "l"(a), "l"(b)); return d;
}

#define BATCH 8
#define H 128
#define W 128
#define OH 127
#define OW 127
#define GX 32
#define TOT_GROUPS (BATCH * OH * GX)

#define WARPS_PER_CTA 8
#define NTHREADS (WARPS_PER_CTA * 32)
#define NCTAS 296

// Cores in smem, swizzled layout (4 KB per block bi):
//   lane L owns lr entries (2L, 2L+1); its 16 float2 (ac=0..15) stored as 8 chunks
//   of 2 ull; chunk c at ull idx  bi*512 + L*16 + ((c + L) & 7) * 2.
//   A chunk (float4) = { cores[ac=2c](lr0), cores[2c](lr1), cores[2c+1](lr0), cores[2c+1](lr1) }.
//
// Per-pair scratch: 640 ull.  M element (bi, row, col): bi*80 + row*10 + col.
//   Overlay: Bsm[rs][k][i] at rs*82 + k*10 + i ; Psm at 336 + (q*8+i)*10 + q*8 + o8.
#define PAIR_ULL 640
#define WARP_ULL (2 * PAIR_ULL)
#define CORES_F 8192
#define SMEM_F  (CORES_F + WARPS_PER_CTA * WARP_ULL * 2)

__global__ void __launch_bounds__(NTHREADS, 2) convsbs_kernel(
    const float* __restrict__ channels,
    const float* __restrict__ cores,
    float* __restrict__ out)
{
    extern __shared__ float smem[];
    const int tid = threadIdx.x;
    ull* coreU = (ull*)smem;

    // cores relayout: [t][q][l][r][a][c4] -> swizzled per-lane chunks (see header)
    for (int idx = tid; idx < 8192; idx += NTHREADS) {
        int c4 = idx & 3, a = (idx >> 2) & 3, r = (idx >> 4) & 7;
        int l = (idx >> 7) & 7, q = (idx >> 10) & 1, t = idx >> 11;
        int bi = t * 2 + q;
        int lr = l * 8 + r;
        int L = lr >> 1, half = lr & 1;
        int ac = a * 4 + c4;
        int chunk = ac >> 1, pos = ac & 1;
        int uidx = bi * 512 + L * 16 + (((chunk + L) & 7) << 1) + pos;
        smem[uidx * 2 + half] = cores[idx];
    }
    __syncthreads();

    const int warp = tid >> 5;
    const int lane = tid & 31;
    ull* Wb = (ull*)(smem + CORES_F) + warp * WARP_ULL;

    const int g2 = lane >> 4;        // q (A-stage) / s (B-stage) / q (final)
    const int i2 = (lane >> 1) & 7;  // i (A) / k (B) / i (final)
    const int h2 = lane & 1;         // k-half (A) / i-half (B)

    const float* __restrict__ ch0 = channels;
    const float* __restrict__ ch1 = channels + BATCH * H * W * 4;
    const ull z = pk2(0.f, 0.f);
    const int nwork = gridDim.x * WARPS_PER_CTA;

    for (int g = blockIdx.x * WARPS_PER_CTA + warp; g < TOT_GROUPS; g += nwork) {
        int b   = g / (OH * GX);
        int rem = g - b * (OH * GX);
        int y   = rem >> 5;
        int x0  = (rem & 31) << 2;

        // ========== Stage 1: M for pairs A=(x0,x0+1), B=(x0+2,x0+3) ==========
        #pragma unroll
        for (int t = 0; t < 4; t++) {
            const int py  = y + (t >> 1);
            const int cxb = x0 + (t & 1);
            float4 c0[4], c1[4];
            #pragma unroll
            for (int d = 0; d < 4; d++) {
                int cx = min(cxb + d, W - 1);
                int base = ((b * H + py) * W + cx) * 4;
                c0[d] = *(const float4*)(ch0 + base);
                c1[d] = *(const float4*)(ch1 + base);
            }
            ull c0A[4], c1A[4], c0B[4], c1B[4];
            c0A[0]=pk2(c0[0].x,c0[1].x); c0A[1]=pk2(c0[0].y,c0[1].y);
            c0A[2]=pk2(c0[0].z,c0[1].z); c0A[3]=pk2(c0[0].w,c0[1].w);
            c1A[0]=pk2(c1[0].x,c1[1].x); c1A[1]=pk2(c1[0].y,c1[1].y);
            c1A[2]=pk2(c1[0].z,c1[1].z); c1A[3]=pk2(c1[0].w,c1[1].w);
            c0B[0]=pk2(c0[2].x,c0[3].x); c0B[1]=pk2(c0[2].y,c0[3].y);
            c0B[2]=pk2(c0[2].z,c0[3].z); c0B[3]=pk2(c0[2].w,c0[3].w);
            c1B[0]=pk2(c1[2].x,c1[3].x); c1B[1]=pk2(c1[2].y,c1[3].y);
            c1B[2]=pk2(c1[2].z,c1[3].z); c1B[3]=pk2(c1[2].w,c1[3].w);

            ull vA[16], vB[16];
            #pragma unroll
            for (int a = 0; a < 4; a++)
                #pragma unroll
                for (int c = 0; c < 4; c++) {
                    vA[a * 4 + c] = mul2(c0A[a], c1A[c]);
                    vB[a * 4 + c] = mul2(c0B[a], c1B[c]);
                }

            const int row = lane >> 2;        // l of entry lr = 2*lane
            const int col = 2 * (lane & 3);   // r of entry lr = 2*lane
            #pragma unroll
            for (int q = 0; q < 2; q++) {
                const int bi = t * 2 + q;
                const float4* cp4 = (const float4*)(coreU + bi * 512 + lane * 16);
                ull aA0 = z, aA1 = z, aB0 = z, aB1 = z;
                #pragma unroll
                for (int c = 0; c < 8; c++) {
                    float4 f = cp4[(c + lane) & 7];   // ac=2c: (f.x,f.y); ac=2c+1: (f.z,f.w)
                    ull cx2 = pk2(f.x, f.x);
                    ull cy2 = pk2(f.y, f.y);
                    aA0 = fma2(cx2, vA[2 * c], aA0);
                    aA1 = fma2(cy2, vA[2 * c], aA1);
                    aB0 = fma2(cx2, vB[2 * c], aB0);
                    aB1 = fma2(cy2, vB[2 * c], aB1);
                    ull cz2 = pk2(f.z, f.z);
                    ull cw2 = pk2(f.w, f.w);
                    aA0 = fma2(cz2, vA[2 * c + 1], aA0);
                    aA1 = fma2(cw2, vA[2 * c + 1], aA1);
                    aB0 = fma2(cz2, vB[2 * c + 1], aB0);
                    aB1 = fma2(cw2, vB[2 * c + 1], aB1);
                }
                const int midx = bi * 80 + row * 10 + col;
                *(ulonglong2*)(Wb + midx)            = make_ulonglong2(aA0, aA1);
                *(ulonglong2*)(Wb + PAIR_ULL + midx) = make_ulonglong2(aB0, aB1);
            }
        }
        __syncwarp();

        // ========== Stage 2 per pair ==========
        #pragma unroll
        for (int pr = 0; pr < 2; pr++) {
            ull* M = Wb + pr * PAIR_ULL;

            // ---- A-stage: lane (q=g2, i=i2, kh=h2), both p accumulated ----
            ull a2[2][4];
            {
                ull rm0[2][8];
                #pragma unroll
                for (int p = 0; p < 2; p++) {
                    #pragma unroll
                    for (int c = 0; c < 4; c++) {
                        ulonglong2 u = *(const ulonglong2*)(M + p * 80 + i2 * 10 + 2 * c);
                        rm0[p][2 * c] = u.x; rm0[p][2 * c + 1] = u.y;
                    }
                }
                #pragma unroll
                for (int p = 0; p < 2; p++)
                    #pragma unroll
                    for (int kk = 0; kk < 4; kk++) a2[p][kk] = z;
                #pragma unroll
                for (int j = 0; j < 8; j++) {
                    ulonglong2 m1a = *(const ulonglong2*)(M + (2 + g2) * 80 + j * 10 + h2 * 4);
                    ulonglong2 m1b = *(const ulonglong2*)(M + (2 + g2) * 80 + j * 10 + h2 * 4 + 2);
                    #pragma unroll
                    for (int p = 0; p < 2; p++) {
                        a2[p][0] = fma2(rm0[p][j], m1a.x, a2[p][0]);
                        a2[p][1] = fma2(rm0[p][j], m1a.y, a2[p][1]);
                        a2[p][2] = fma2(rm0[p][j], m1b.x, a2[p][2]);
                        a2[p][3] = fma2(rm0[p][j], m1b.y, a2[p][3]);
                    }
                }
            }

            // ---- B-stage: lane (s=g2, k=i2, ih=h2), both r accumulated ----
            ull bt[2][4];
            {
                ull rm2[2][8];
                #pragma unroll
                for (int r = 0; r < 2; r++) {
                    #pragma unroll
                    for (int c = 0; c < 4; c++) {
                        ulonglong2 u = *(const ulonglong2*)(M + (4 + r) * 80 + i2 * 10 + 2 * c);
                        rm2[r][2 * c] = u.x; rm2[r][2 * c + 1] = u.y;
                    }
                }
                #pragma unroll
                for (int r = 0; r < 2; r++)
                    #pragma unroll
                    for (int ii = 0; ii < 4; ii++) bt[r][ii] = z;
                #pragma unroll
                for (int l = 0; l < 8; l++) {
                    ulonglong2 m3a = *(const ulonglong2*)(M + (6 + g2) * 80 + l * 10 + h2 * 4);
                    ulonglong2 m3b = *(const ulonglong2*)(M + (6 + g2) * 80 + l * 10 + h2 * 4 + 2);
                    #pragma unroll
                    for (int r = 0; r < 2; r++) {
                        bt[r][0] = fma2(rm2[r][l], m3a.x, bt[r][0]);
                        bt[r][1] = fma2(rm2[r][l], m3a.y, bt[r][1]);
                        bt[r][2] = fma2(rm2[r][l], m3b.x, bt[r][2]);
                        bt[r][3] = fma2(rm2[r][l], m3b.y, bt[r][3]);
                    }
                }
            }
            __syncwarp();

            // ---- store B: Bsm[rs][k][i] at rs*82 + k*10 + i  (rs = r*2 + s) ----
            #pragma unroll
            for (int r = 0; r < 2; r++) {
                const int base = (r * 2 + g2) * 82 + i2 * 10 + h2 * 4;
                *(ulonglong2*)(M + base)     = make_ulonglong2(bt[r][0], bt[r][1]);
                *(ulonglong2*)(M + base + 2) = make_ulonglong2(bt[r][2], bt[r][3]);
            }
            __syncwarp();

            // ---- final partials at lane (q=g2, i=i2, kh=h2) ----
            ull part[2][4];
            #pragma unroll
            for (int p = 0; p < 2; p++)
                #pragma unroll
                for (int rs = 0; rs < 4; rs++) part[p][rs] = z;
            #pragma unroll
            for (int rs = 0; rs < 4; rs++) {
                #pragma unroll
                for (int kk = 0; kk < 4; kk++) {
                    ull Bv = M[rs * 82 + (h2 * 4 + kk) * 10 + i2];
                    part[0][rs] = fma2(a2[0][kk], Bv, part[0][rs]);
                    part[1][rs] = fma2(a2[1][kk], Bv, part[1][rs]);
                }
            }
            #pragma unroll
            for (int p = 0; p < 2; p++)
                #pragma unroll
                for (int rs = 0; rs < 4; rs++)
                    part[p][rs] = add2(part[p][rs],
                                       __shfl_xor_sync(0xffffffffu, part[p][rs], 1));
            if (h2 == 0) {
                const int pbase = 336 + (g2 * 8 + i2) * 10 + g2 * 8;
                *(ulonglong2*)(M + pbase)     = make_ulonglong2(part[0][0], part[0][1]);
                *(ulonglong2*)(M + pbase + 2) = make_ulonglong2(part[0][2], part[0][3]);
                *(ulonglong2*)(M + pbase + 4) = make_ulonglong2(part[1][0], part[1][1]);
                *(ulonglong2*)(M + pbase + 6) = make_ulonglong2(part[1][2], part[1][3]);
            }
            __syncwarp();

            // ---- output: lanes 0..15, q=lane>>3, o8=lane&7 (p=o8>>2, rs=o8&3) ----
            if (lane < 16) {
                const int q = lane >> 3, o8 = lane & 7;
                ull s = z;
                #pragma unroll
                for (int i = 0; i < 8; i++)
                    s = add2(s, M[336 + (q * 8 + i) * 10 + q * 8 + o8]);
                const int p = o8 >> 2, rs = o8 & 3;
                const int outIdx = p * 8 + q * 4 + rs;
                const int xx = x0 + pr * 2;
                const int pix0 = (b * OH + y) * OW + xx;
                float2 pv = up2(s);
                out[pix0 * 16 + outIdx] = pv.x;
                if (xx + 1 < OW)
                    out[(pix0 + 1) * 16 + outIdx] = pv.y;
            }
            __syncwarp();
        }
    }
}

extern "C" void kernel_launch(void* const* d_in, const int* in_sizes, int n_in,
                              void* d_out, int out_size)
{
    const float* channels = (const float*)d_in[0];
    const float* cores    = (const float*)d_in[1];
    float* out            = (float*)d_out;

    static bool attr_set = false;
    if (!attr_set) {
        cudaFuncSetAttribute(convsbs_kernel,
                             cudaFuncAttributeMaxDynamicSharedMemorySize,
                             SMEM_F * sizeof(float));
        attr_set = true;
    }
    convsbs_kernel<<<NCTAS, NTHREADS, SMEM_F * sizeof(float)>>>(channels, cores, out);
}